// round 13
// baseline (speedup 1.0000x reference)
#include <cuda_runtime.h>
#include <cuda_bf16.h>
#include <cstdint>

#define BB 4
#define SS 2048
#define HH 1024
#define MM (BB*SS)
#define HHHH ((long long)HH*HH)
#define MMHH ((long long)MM*HH)

typedef __nv_bfloat16 bf16;
typedef __nv_bfloat162 bf162;

// ---------------- scratch ----------------
__device__ bf16  g_Xh[MM*HH], g_Xl[MM*HH];
__device__ bf16  g_Wqkvh[3*HH*HH], g_Wqkvl[3*HH*HH];   // Wq|Wk|Wv contiguous slabs
__device__ bf16  g_Woh[HH*HH], g_Wol[HH*HH];
__device__ bf16  g_QKh[2*MM*HH], g_QKl[2*MM*HH];       // Q slab | K slab
__device__ bf16  g_Vth[MM*HH], g_Vtl[MM*HH];
__device__ float g_S[(long long)BB*SS*SS];
__device__ bf16  g_Ph[BB*SS*SS], g_Pl[BB*SS*SS];
__device__ bf16  g_Ch[MM*HH], g_Cl[MM*HH];
__device__ float g_x[(long long)MM*HH];
__device__ float g_wddp[MM*32];

// ---------------- helpers ----------------
__device__ __forceinline__ uint32_t smem_u32(const void* p){
    uint32_t a;
    asm("{ .reg .u64 t; cvta.to.shared.u64 t, %1; cvt.u32.u64 %0, t; }" : "=r"(a) : "l"(p));
    return a;
}
#define LDSM4(r0,r1,r2,r3,addr) \
    asm volatile("ldmatrix.sync.aligned.m8n8.x4.shared.b16 {%0,%1,%2,%3}, [%4];" \
        : "=r"(r0),"=r"(r1),"=r"(r2),"=r"(r3) : "r"(addr))
#define MMA_BF16(d0,d1,d2,d3, a0,a1,a2,a3, b0,b1) \
    asm volatile("mma.sync.aligned.m16n8k16.row.col.f32.bf16.bf16.f32 " \
        "{%0,%1,%2,%3}, {%4,%5,%6,%7}, {%8,%9}, {%0,%1,%2,%3};" \
        : "+f"(d0),"+f"(d1),"+f"(d2),"+f"(d3) \
        : "r"(a0),"r"(a1),"r"(a2),"r"(a3), "r"(b0),"r"(b1))
#define CP16(dst, src) asm volatile("cp.async.cg.shared.global [%0], [%1], 16;" :: "r"(dst), "l"(src))
#define CPCOMMIT() asm volatile("cp.async.commit_group;" ::: "memory")
#define CPWAIT(n)  asm volatile("cp.async.wait_group %0;" :: "n"(n) : "memory")

__device__ __forceinline__ uint32_t bfbits(bf162 h){ return *reinterpret_cast<uint32_t*>(&h); }

__device__ __forceinline__ void split2(float2 v, uint32_t& h, uint32_t& l){
    bf162 h2 = __float22bfloat162_rn(v);
    float2 hf = __bfloat1622float2(h2);
    bf162 l2 = __float22bfloat162_rn(make_float2(v.x - hf.x, v.y - hf.y));
    h = bfbits(h2); l = bfbits(l2);
}

// swizzled byte offset of 16B chunk (row r, k-chunk c in 0..7) in a [rows][64] bf16 tile
__device__ __forceinline__ uint32_t toff8(int r, int c){
    return (uint32_t)(r * 128 + ((c ^ (r & 7)) << 4));
}

// ---------------- split kernels ----------------
__global__ __launch_bounds__(256)
void split_kernel(const float* __restrict__ src, bf16* __restrict__ hi,
                  bf16* __restrict__ lo, int n4)
{
    int i = blockIdx.x * 256 + threadIdx.x;
    if (i >= n4) return;
    float4 v = *(const float4*)(src + (long long)i * 4);
    uint2 h, l;
    split2(make_float2(v.x, v.y), h.x, l.x);
    split2(make_float2(v.z, v.w), h.y, l.y);
    *(uint2*)(hi + (long long)i * 4) = h;
    *(uint2*)(lo + (long long)i * 4) = l;
}

// split 4 weights: Wq/Wk/Wv -> contiguous slabs, Wo -> separate
__global__ __launch_bounds__(256)
void split4_kernel(const float* s0, const float* s1, const float* s2, const float* s3,
                   bf16* qkvh, bf16* qkvl, bf16* oh, bf16* ol, int n4)
{
    int w = blockIdx.y;
    const float* src = (w == 0) ? s0 : (w == 1) ? s1 : (w == 2) ? s2 : s3;
    bf16* hi = (w < 3) ? qkvh + (long long)w * HHHH : oh;
    bf16* lo = (w < 3) ? qkvl + (long long)w * HHHH : ol;
    int i = blockIdx.x * 256 + threadIdx.x;
    if (i >= n4) return;
    float4 v = *(const float4*)(src + (long long)i * 4);
    uint2 h, l;
    split2(make_float2(v.x, v.y), h.x, l.x);
    split2(make_float2(v.z, v.w), h.y, l.y);
    *(uint2*)(hi + (long long)i * 4) = h;
    *(uint2*)(lo + (long long)i * 4) = l;
}

// ---------------- GEMM config (shared) ----------------
constexpr int STAGE = 49152;
constexpr int OA_HI = 0, OA_LO = 16384, OB_HI = 32768, OB_LO = 40960;
constexpr int SMEM_DYN = 2 * STAGE;      // 96 KB -> 2 CTAs/SM

// software-pipelined mainloop: per ks, issue ALL LDSMs (bl/al + next-ks ah/bh
// prefetch, double-buffered on ks&1) BEFORE the 24 MMAs, so fragment-load
// latency hides under MMA issue instead of stalling each phase.
#define GEMM_MAINLOOP(Kdim)                                                         \
    const int NC = (Kdim) / 64;                                                     \
    issue(0, 0);                                                                    \
    for (int it = 0; it < NC; it++) {                                               \
        const int buf = it & 1;                                                     \
        if (it + 1 < NC) { issue(it + 1, buf ^ 1); CPWAIT(1); }                     \
        else             { CPWAIT(0); }                                             \
        __syncthreads();                                                            \
        const uint32_t stg = sb + buf * STAGE;                                      \
        const uint32_t stAh = stg + OA_HI;                                          \
        const uint32_t stAl = stg + OA_LO;                                          \
        const uint32_t stBh = stg + OB_HI;                                          \
        const uint32_t stBl = stg + OB_LO;                                          \
        const int rA0 = m0w + (lane & 15);                                          \
        const int rB  = n0w + lane;                                                 \
        const int cah = (lane >> 4);                                                \
        uint32_t ah[2][2][4], bh[2][4][2];                                          \
        _Pragma("unroll")                                                           \
        for (int mf = 0; mf < 2; mf++)                                              \
            LDSM4(ah[0][mf][0], ah[0][mf][1], ah[0][mf][2], ah[0][mf][3],           \
                  stAh + toff8(rA0 + mf * 16, cah));                                \
        _Pragma("unroll")                                                           \
        for (int h = 0; h < 2; h++)                                                 \
            LDSM4(bh[0][0][h], bh[0][1][h], bh[0][2][h], bh[0][3][h],               \
                  stBh + toff8(rB, h));                                             \
        _Pragma("unroll")                                                           \
        for (int ks = 0; ks < 4; ks++) {                                            \
            const int cur = ks & 1, nxt = cur ^ 1;                                  \
            const int ca = ks * 2 + cah;                                            \
            uint32_t bl[4][2], al[2][4];                                            \
            _Pragma("unroll")                                                       \
            for (int h = 0; h < 2; h++)                                             \
                LDSM4(bl[0][h], bl[1][h], bl[2][h], bl[3][h],                       \
                      stBl + toff8(rB, ks * 2 + h));                                \
            _Pragma("unroll")                                                       \
            for (int mf = 0; mf < 2; mf++)                                          \
                LDSM4(al[mf][0], al[mf][1], al[mf][2], al[mf][3],                   \
                      stAl + toff8(rA0 + mf * 16, ca));                             \
            if (ks < 3) {                                                           \
                _Pragma("unroll")                                                   \
                for (int mf = 0; mf < 2; mf++)                                      \
                    LDSM4(ah[nxt][mf][0], ah[nxt][mf][1], ah[nxt][mf][2], ah[nxt][mf][3], \
                          stAh + toff8(rA0 + mf * 16, ca + 2));                     \
                _Pragma("unroll")                                                   \
                for (int h = 0; h < 2; h++)                                         \
                    LDSM4(bh[nxt][0][h], bh[nxt][1][h], bh[nxt][2][h], bh[nxt][3][h], \
                          stBh + toff8(rB, (ks + 1) * 2 + h));                      \
            }                                                                       \
            _Pragma("unroll")                                                       \
            for (int mf = 0; mf < 2; mf++)                                          \
                _Pragma("unroll")                                                   \
                for (int nf = 0; nf < 4; nf++)                                      \
                    MMA_BF16(acc[mf][nf][0], acc[mf][nf][1], acc[mf][nf][2], acc[mf][nf][3], \
                             ah[cur][mf][0], ah[cur][mf][1], ah[cur][mf][2], ah[cur][mf][3], \
                             bh[cur][nf][0], bh[cur][nf][1]);                       \
            _Pragma("unroll")                                                       \
            for (int mf = 0; mf < 2; mf++)                                          \
                _Pragma("unroll")                                                   \
                for (int nf = 0; nf < 4; nf++)                                      \
                    MMA_BF16(acc[mf][nf][0], acc[mf][nf][1], acc[mf][nf][2], acc[mf][nf][3], \
                             ah[cur][mf][0], ah[cur][mf][1], ah[cur][mf][2], ah[cur][mf][3], \
                             bl[nf][0], bl[nf][1]);                                 \
            _Pragma("unroll")                                                       \
            for (int mf = 0; mf < 2; mf++)                                          \
                _Pragma("unroll")                                                   \
                for (int nf = 0; nf < 4; nf++)                                      \
                    MMA_BF16(acc[mf][nf][0], acc[mf][nf][1], acc[mf][nf][2], acc[mf][nf][3], \
                             al[mf][0], al[mf][1], al[mf][2], al[mf][3],            \
                             bh[cur][nf][0], bh[cur][nf][1]);                       \
        }                                                                           \
        __syncthreads();                                                            \
    }

// ---------------- fused QKV projection GEMM ----------------
// z=0: Q (split out + wdd partials), z=1: K (split out), z=2: V (transposed split out)
__global__ __launch_bounds__(256, 2)
void tgemm_qkv(const bf16* __restrict__ Ah, const bf16* __restrict__ Al,
               const bf16* __restrict__ Wh, const bf16* __restrict__ Wl,
               const float* __restrict__ bq, const float* __restrict__ bk,
               const float* __restrict__ bv,
               bf16* __restrict__ QKh, bf16* __restrict__ QKl,
               bf16* __restrict__ Vth, bf16* __restrict__ Vtl,
               float* __restrict__ wddp, const float* __restrict__ dist1)
{
    extern __shared__ __align__(128) uint8_t sm[];
    const uint32_t sb = smem_u32(sm);
    const int tid = threadIdx.x;
    const int wid = tid >> 5;
    const int lane = tid & 31;
    const int z = blockIdx.z;
    const int row0 = blockIdx.y * 128;
    const int col0 = blockIdx.x * 64;
    const bf16* Ahp = Ah;
    const bf16* Alp = Al;
    const bf16* Bhp = Wh + (long long)z * HHHH;
    const bf16* Blp = Wl + (long long)z * HHHH;

    const int m0w = (wid & 3) * 32;
    const int n0w = (wid >> 2) * 32;
    const int rl = tid >> 3;
    const int cl = tid & 7;

    float acc[2][4][4];
    #pragma unroll
    for (int i = 0; i < 2; i++)
        #pragma unroll
        for (int j = 0; j < 4; j++)
            #pragma unroll
            for (int c = 0; c < 4; c++) acc[i][j][c] = 0.f;

    auto issue = [&](int it, int buf) {
        const int k0 = it * 64;
        const uint32_t st = sb + buf * STAGE;
        #pragma unroll
        for (int rr = 0; rr < 128; rr += 32) {
            const int r = rl + rr;
            const uint32_t o = toff8(r, cl);
            const long long aoff = (long long)(row0 + r) * HH + k0 + cl * 8;
            CP16(st + OA_HI + o, Ahp + aoff);
            CP16(st + OA_LO + o, Alp + aoff);
        }
        #pragma unroll
        for (int rr = 0; rr < 64; rr += 32) {
            const int r = rl + rr;
            const uint32_t o = toff8(r, cl);
            const long long boff = (long long)(col0 + r) * HH + k0 + cl * 8;
            CP16(st + OB_HI + o, Bhp + boff);
            CP16(st + OB_LO + o, Blp + boff);
        }
        CPCOMMIT();
    };

    GEMM_MAINLOOP(HH)

    const float* bias = (z == 0) ? bq : (z == 1) ? bk : bv;
    const int cr = lane >> 2;
    const int cc = (lane & 3) * 2;
    #pragma unroll
    for (int mf = 0; mf < 2; mf++) {
        #pragma unroll
        for (int half = 0; half < 2; half++) {
            const int r = row0 + m0w + mf * 16 + cr + half * 8;
            float wpart = 0.f;
            #pragma unroll
            for (int nf = 0; nf < 4; nf++) {
                const int c = col0 + n0w + nf * 8 + cc;
                float2 v;
                v.x = acc[mf][nf][half * 2 + 0] + bias[c];
                v.y = acc[mf][nf][half * 2 + 1] + bias[c + 1];
                if (z < 2) {
                    const long long rb = (long long)z * MMHH + (long long)r * HH;
                    uint32_t h, l;
                    split2(v, h, l);
                    *(uint32_t*)(QKh + rb + c) = h;
                    *(uint32_t*)(QKl + rb + c) = l;
                    if (z == 0) {
                        float2 dv = *(const float2*)(dist1 + c);
                        wpart = fmaf(v.x, dv.x, fmaf(v.y, dv.y, wpart));
                    }
                } else {
                    const int b = r >> 11;
                    const int s = r & (SS - 1);
                    const long long base = (long long)b * HH * SS + s;
                    bf162 h2 = __float22bfloat162_rn(v);
                    float2 hf = __bfloat1622float2(h2);
                    bf162 l2 = __float22bfloat162_rn(make_float2(v.x - hf.x, v.y - hf.y));
                    Vth[base + (long long)c * SS]       = h2.x;
                    Vth[base + (long long)(c + 1) * SS] = h2.y;
                    Vtl[base + (long long)c * SS]       = l2.x;
                    Vtl[base + (long long)(c + 1) * SS] = l2.y;
                }
            }
            if (z == 0) {
                wpart += __shfl_xor_sync(0xffffffffu, wpart, 1);
                wpart += __shfl_xor_sync(0xffffffffu, wpart, 2);
                if ((lane & 3) == 0)
                    wddp[(long long)r * 32 + blockIdx.x * 2 + (wid >> 2)] = wpart;
            }
        }
    }
}

// ---------------- generic split-bf16 GEMM (scores / PV / out-proj) ----------------
// OUTMODE 0: fp32 out (+bias +resid). OUTMODE 1: bf16 hi/lo out.
template<int OUTMODE>
__global__ __launch_bounds__(256, 2)
void tgemm(const bf16* __restrict__ Ah, const bf16* __restrict__ Al,
           const bf16* __restrict__ Bh, const bf16* __restrict__ Bl,
           const float* __restrict__ bias, const float* __restrict__ resid,
           float* __restrict__ Cf, bf16* __restrict__ Ch, bf16* __restrict__ Cl,
           int N, int K, long long sA, long long sB, long long sC)
{
    extern __shared__ __align__(128) uint8_t sm[];
    const uint32_t sb = smem_u32(sm);
    const int tid = threadIdx.x;
    const int wid = tid >> 5;
    const int lane = tid & 31;
    const int row0 = blockIdx.y * 128;
    const int col0 = blockIdx.x * 64;
    const bf16* Ahp = Ah + blockIdx.z * sA;
    const bf16* Alp = Al + blockIdx.z * sA;
    const bf16* Bhp = Bh + blockIdx.z * sB;
    const bf16* Blp = Bl + blockIdx.z * sB;

    const int m0w = (wid & 3) * 32;
    const int n0w = (wid >> 2) * 32;
    const int rl = tid >> 3;
    const int cl = tid & 7;

    float acc[2][4][4];
    #pragma unroll
    for (int i = 0; i < 2; i++)
        #pragma unroll
        for (int j = 0; j < 4; j++)
            #pragma unroll
            for (int c = 0; c < 4; c++) acc[i][j][c] = 0.f;

    auto issue = [&](int it, int buf) {
        const int k0 = it * 64;
        const uint32_t st = sb + buf * STAGE;
        #pragma unroll
        for (int rr = 0; rr < 128; rr += 32) {
            const int r = rl + rr;
            const uint32_t o = toff8(r, cl);
            const long long aoff = (long long)(row0 + r) * K + k0 + cl * 8;
            CP16(st + OA_HI + o, Ahp + aoff);
            CP16(st + OA_LO + o, Alp + aoff);
        }
        #pragma unroll
        for (int rr = 0; rr < 64; rr += 32) {
            const int r = rl + rr;
            const uint32_t o = toff8(r, cl);
            const long long boff = (long long)(col0 + r) * K + k0 + cl * 8;
            CP16(st + OB_HI + o, Bhp + boff);
            CP16(st + OB_LO + o, Blp + boff);
        }
        CPCOMMIT();
    };

    GEMM_MAINLOOP(K)

    const int cr = lane >> 2;
    const int cc = (lane & 3) * 2;
    #pragma unroll
    for (int mf = 0; mf < 2; mf++) {
        #pragma unroll
        for (int half = 0; half < 2; half++) {
            const int r = row0 + m0w + mf * 16 + cr + half * 8;
            const long long rb = (long long)r * N;
            #pragma unroll
            for (int nf = 0; nf < 4; nf++) {
                const int c = col0 + n0w + nf * 8 + cc;
                float2 v;
                v.x = acc[mf][nf][half * 2 + 0];
                v.y = acc[mf][nf][half * 2 + 1];
                if (bias) {
                    float2 bv = *(const float2*)(bias + c);
                    v.x += bv.x; v.y += bv.y;
                }
                if (OUTMODE == 0) {
                    if (resid) {
                        float2 rv = *(const float2*)(resid + blockIdx.z * sC + rb + c);
                        v.x += rv.x; v.y += rv.y;
                    }
                    *(float2*)(Cf + blockIdx.z * sC + rb + c) = v;
                } else {
                    uint32_t h, l;
                    split2(v, h, l);
                    *(uint32_t*)(Ch + blockIdx.z * sC + rb + c) = h;
                    *(uint32_t*)(Cl + blockIdx.z * sC + rb + c) = l;
                }
            }
        }
    }
}

// ---------------- softmax -> P hi/lo (vectorized, sums wdd partials) ----------------
__global__ __launch_bounds__(256)
void softmax_kernel(const float* __restrict__ S, const int* __restrict__ rel,
                    const float* __restrict__ mask, const float* __restrict__ wddp,
                    bf16* __restrict__ Ph, bf16* __restrict__ Pl)
{
    const long long row = blockIdx.x;
    const int b = (int)(row >> 11);
    const float4* s4 = (const float4*)(S + row * (long long)SS);
    const int4*   r4 = (const int4*)(rel + row * (long long)SS);
    const float4* m4 = (const float4*)(mask + (long long)b * SS);

    __shared__ float swdd;
    if (threadIdx.x < 32) {
        float p = wddp[row * 32 + threadIdx.x];
        #pragma unroll
        for (int o = 16; o; o >>= 1) p += __shfl_xor_sync(0xffffffffu, p, o);
        if (threadIdx.x == 0) swdd = p;
    }
    __syncthreads();
    const float w = swdd;

    float4 vals[2];
    float mx = -1e30f;
    #pragma unroll
    for (int i = 0; i < 2; i++) {
        const int idx = threadIdx.x + i * 256;
        float4 sv = s4[idx];
        int4   rv = r4[idx];
        float4 mv = m4[idx];
        sv.x = (rv.x == 1 ? sv.x + w : sv.x) * 0.03125f + mv.x;
        sv.y = (rv.y == 1 ? sv.y + w : sv.y) * 0.03125f + mv.y;
        sv.z = (rv.z == 1 ? sv.z + w : sv.z) * 0.03125f + mv.z;
        sv.w = (rv.w == 1 ? sv.w + w : sv.w) * 0.03125f + mv.w;
        vals[i] = sv;
        mx = fmaxf(mx, fmaxf(fmaxf(sv.x, sv.y), fmaxf(sv.z, sv.w)));
    }
    __shared__ float shm[8], shs[8];
    #pragma unroll
    for (int o = 16; o; o >>= 1) mx = fmaxf(mx, __shfl_xor_sync(0xffffffffu, mx, o));
    if ((threadIdx.x & 31) == 0) shm[threadIdx.x >> 5] = mx;
    __syncthreads();
    mx = shm[0];
    #pragma unroll
    for (int i = 1; i < 8; i++) mx = fmaxf(mx, shm[i]);

    float tot = 0.f;
    #pragma unroll
    for (int i = 0; i < 2; i++) {
        vals[i].x = __expf(vals[i].x - mx);
        vals[i].y = __expf(vals[i].y - mx);
        vals[i].z = __expf(vals[i].z - mx);
        vals[i].w = __expf(vals[i].w - mx);
        tot += vals[i].x + vals[i].y + vals[i].z + vals[i].w;
    }
    #pragma unroll
    for (int o = 16; o; o >>= 1) tot += __shfl_xor_sync(0xffffffffu, tot, o);
    if ((threadIdx.x & 31) == 0) shs[threadIdx.x >> 5] = tot;
    __syncthreads();
    tot = 0.f;
    #pragma unroll
    for (int i = 0; i < 8; i++) tot += shs[i];

    const float inv = 1.f / tot;
    uint2* ph2 = (uint2*)(Ph + row * (long long)SS);
    uint2* pl2 = (uint2*)(Pl + row * (long long)SS);
    #pragma unroll
    for (int i = 0; i < 2; i++) {
        const int idx = threadIdx.x + i * 256;
        float4 p = vals[i];
        p.x *= inv; p.y *= inv; p.z *= inv; p.w *= inv;
        uint2 h, l;
        split2(make_float2(p.x, p.y), h.x, l.x);
        split2(make_float2(p.z, p.w), h.y, l.y);
        ph2[idx] = h;
        pl2[idx] = l;
    }
}

// ---------------- LayerNorm (vectorized) ----------------
__global__ __launch_bounds__(256)
void ln_kernel(const float* __restrict__ X, const float* __restrict__ g,
               const float* __restrict__ bb, float* __restrict__ out)
{
    const long long row = blockIdx.x;
    const float4* x4 = (const float4*)(X + row * HH);
    float4 v = x4[threadIdx.x];
    float sum = v.x + v.y + v.z + v.w;
    float sq = fmaf(v.x, v.x, fmaf(v.y, v.y, fmaf(v.z, v.z, v.w * v.w)));

    __shared__ float s1[8], s2[8];
    #pragma unroll
    for (int o = 16; o; o >>= 1) {
        sum += __shfl_xor_sync(0xffffffffu, sum, o);
        sq  += __shfl_xor_sync(0xffffffffu, sq, o);
    }
    if ((threadIdx.x & 31) == 0) { s1[threadIdx.x >> 5] = sum; s2[threadIdx.x >> 5] = sq; }
    __syncthreads();
    sum = 0.f; sq = 0.f;
    #pragma unroll
    for (int i = 0; i < 8; i++) { sum += s1[i]; sq += s2[i]; }

    const float mean = sum * (1.f / HH);
    const float var  = sq * (1.f / HH) - mean * mean;
    const float inv  = rsqrtf(var + 1e-12f);

    const float4 gv = ((const float4*)g)[threadIdx.x];
    const float4 bv = ((const float4*)bb)[threadIdx.x];
    float4 o;
    o.x = (v.x - mean) * inv * gv.x + bv.x;
    o.y = (v.y - mean) * inv * gv.y + bv.y;
    o.z = (v.z - mean) * inv * gv.z + bv.z;
    o.w = (v.w - mean) * inv * gv.w + bv.w;
    ((float4*)(out + row * HH))[threadIdx.x] = o;
}

// ---------------- launch ----------------
extern "C" void kernel_launch(void* const* d_in, const int* in_sizes, int n_in,
                              void* d_out, int out_size)
{
    const float* hidden = (const float*)d_in[0];
    const float* amask  = (const float*)d_in[1];
    const int*   rel    = (const int*)d_in[2];
    const float* Wq = (const float*)d_in[3];
    const float* bq = (const float*)d_in[4];
    const float* Wk = (const float*)d_in[5];
    const float* bk = (const float*)d_in[6];
    const float* Wv = (const float*)d_in[7];
    const float* bv = (const float*)d_in[8];
    const float* dist = (const float*)d_in[9];
    const float* Wo = (const float*)d_in[10];
    const float* bo = (const float*)d_in[11];
    const float* lng = (const float*)d_in[12];
    const float* lnb = (const float*)d_in[13];
    float* out = (float*)d_out;

    bf16 *Xh,*Xl,*Wqkvh,*Wqkvl,*Woh,*Wol;
    bf16 *QKh,*QKl,*Vth,*Vtl,*Ph,*Pl,*Ch,*Cl;
    float *Sp,*Xp,*Wpp;
    cudaGetSymbolAddress((void**)&Xh, g_Xh);     cudaGetSymbolAddress((void**)&Xl, g_Xl);
    cudaGetSymbolAddress((void**)&Wqkvh, g_Wqkvh); cudaGetSymbolAddress((void**)&Wqkvl, g_Wqkvl);
    cudaGetSymbolAddress((void**)&Woh, g_Woh);   cudaGetSymbolAddress((void**)&Wol, g_Wol);
    cudaGetSymbolAddress((void**)&QKh, g_QKh);   cudaGetSymbolAddress((void**)&QKl, g_QKl);
    cudaGetSymbolAddress((void**)&Vth, g_Vth);   cudaGetSymbolAddress((void**)&Vtl, g_Vtl);
    cudaGetSymbolAddress((void**)&Ph, g_Ph);     cudaGetSymbolAddress((void**)&Pl, g_Pl);
    cudaGetSymbolAddress((void**)&Ch, g_Ch);     cudaGetSymbolAddress((void**)&Cl, g_Cl);
    cudaGetSymbolAddress((void**)&Sp, g_S);
    cudaGetSymbolAddress((void**)&Xp, g_x);
    cudaGetSymbolAddress((void**)&Wpp, g_wddp);

    cudaFuncSetAttribute(tgemm_qkv, cudaFuncAttributeMaxDynamicSharedMemorySize, SMEM_DYN);
    cudaFuncSetAttribute(tgemm<0>, cudaFuncAttributeMaxDynamicSharedMemorySize, SMEM_DYN);
    cudaFuncSetAttribute(tgemm<1>, cudaFuncAttributeMaxDynamicSharedMemorySize, SMEM_DYN);

    dim3 blk(256);

    split_kernel<<<MM * HH / 4 / 256, blk>>>(hidden, Xh, Xl, MM * HH / 4);
    split4_kernel<<<dim3(HH * HH / 4 / 256, 4), blk>>>(
        Wq, Wk, Wv, Wo, Wqkvh, Wqkvl, Woh, Wol, HH * HH / 4);

    dim3 tb(256);
    // fused QKV projection: grid z = 0(Q),1(K),2(V)
    tgemm_qkv<<<dim3(HH / 64, MM / 128, 3), tb, SMEM_DYN>>>(
        Xh, Xl, Wqkvh, Wqkvl, bq, bk, bv,
        QKh, QKl, Vth, Vtl, Wpp, dist + HH);

    // scores: per batch QK^T -> fp32 S
    dim3 gs(SS / 64, SS / 128, BB);
    tgemm<0><<<gs, tb, SMEM_DYN>>>(QKh, QKl, QKh + MMHH, QKl + MMHH, nullptr, nullptr,
                                   Sp, nullptr, nullptr, SS, HH,
                                   (long long)SS * HH, (long long)SS * HH, (long long)SS * SS);

    // softmax -> P hi/lo
    softmax_kernel<<<MM, blk>>>(Sp, rel, amask, Wpp, Ph, Pl);

    // ctx: per batch P . Vt^T -> ctx hi/lo
    dim3 gp(HH / 64, SS / 128, BB);
    tgemm<1><<<gp, tb, SMEM_DYN>>>(Ph, Pl, Vth, Vtl, nullptr, nullptr,
                                   nullptr, Ch, Cl, HH, SS,
                                   (long long)SS * SS, (long long)HH * SS, (long long)SS * HH);

    // out projection + bias + residual -> fp32 x
    dim3 go(HH / 64, MM / 128, 1);
    tgemm<0><<<go, tb, SMEM_DYN>>>(Ch, Cl, Woh, Wol, bo, hidden,
                                   Xp, nullptr, nullptr, HH, HH, 0, 0, 0);

    ln_kernel<<<MM, blk>>>(Xp, lng, lnb, out);
}

// round 14
// speedup vs baseline: 1.0040x; 1.0040x over previous
#include <cuda_runtime.h>
#include <cuda_bf16.h>
#include <cstdint>

#define BB 4
#define SS 2048
#define HH 1024
#define MM (BB*SS)
#define HHHH ((long long)HH*HH)
#define MMHH ((long long)MM*HH)

typedef __nv_bfloat16 bf16;
typedef __nv_bfloat162 bf162;

// ---------------- scratch ----------------
__device__ bf16  g_Xh[MM*HH], g_Xl[MM*HH];
__device__ bf16  g_Wqkvh[3*HH*HH], g_Wqkvl[3*HH*HH];   // Wq|Wk|Wv contiguous slabs
__device__ bf16  g_Woh[HH*HH], g_Wol[HH*HH];
__device__ bf16  g_QKh[2*MM*HH], g_QKl[2*MM*HH];       // Q slab | K slab
__device__ bf16  g_Vth[MM*HH], g_Vtl[MM*HH];
__device__ float g_S[(long long)BB*SS*SS];
__device__ bf16  g_Ph[BB*SS*SS], g_Pl[BB*SS*SS];
__device__ bf16  g_Ch[MM*HH], g_Cl[MM*HH];
__device__ float g_x[(long long)MM*HH];
__device__ float g_wddp[MM*32];

// ---------------- helpers ----------------
__device__ __forceinline__ uint32_t smem_u32(const void* p){
    uint32_t a;
    asm("{ .reg .u64 t; cvta.to.shared.u64 t, %1; cvt.u32.u64 %0, t; }" : "=r"(a) : "l"(p));
    return a;
}
#define LDSM4(r0,r1,r2,r3,addr) \
    asm volatile("ldmatrix.sync.aligned.m8n8.x4.shared.b16 {%0,%1,%2,%3}, [%4];" \
        : "=r"(r0),"=r"(r1),"=r"(r2),"=r"(r3) : "r"(addr))
#define MMA_BF16(d0,d1,d2,d3, a0,a1,a2,a3, b0,b1) \
    asm volatile("mma.sync.aligned.m16n8k16.row.col.f32.bf16.bf16.f32 " \
        "{%0,%1,%2,%3}, {%4,%5,%6,%7}, {%8,%9}, {%0,%1,%2,%3};" \
        : "+f"(d0),"+f"(d1),"+f"(d2),"+f"(d3) \
        : "r"(a0),"r"(a1),"r"(a2),"r"(a3), "r"(b0),"r"(b1))
#define CP16(dst, src) asm volatile("cp.async.cg.shared.global [%0], [%1], 16;" :: "r"(dst), "l"(src))
#define CPCOMMIT() asm volatile("cp.async.commit_group;" ::: "memory")
#define CPWAIT(n)  asm volatile("cp.async.wait_group %0;" :: "n"(n) : "memory")

__device__ __forceinline__ uint32_t bfbits(bf162 h){ return *reinterpret_cast<uint32_t*>(&h); }

__device__ __forceinline__ void split2(float2 v, uint32_t& h, uint32_t& l){
    bf162 h2 = __float22bfloat162_rn(v);
    float2 hf = __bfloat1622float2(h2);
    bf162 l2 = __float22bfloat162_rn(make_float2(v.x - hf.x, v.y - hf.y));
    h = bfbits(h2); l = bfbits(l2);
}

// swizzled byte offset of 16B chunk (row r, k-chunk c in 0..7) in a [rows][64] bf16 tile
__device__ __forceinline__ uint32_t toff8(int r, int c){
    return (uint32_t)(r * 128 + ((c ^ (r & 7)) << 4));
}

// ---------------- fused split: X + all 4 weights in one launch ----------------
// blocks [0, 8192): X ; [8192, 12288): Wq/Wk/Wv/Wo (1024 blocks each)
constexpr int XBLKS = MM * HH / 4 / 256;    // 8192
constexpr int WBLKS = HH * HH / 4 / 256;    // 1024

__global__ __launch_bounds__(256)
void split_all(const float* __restrict__ X,
               const float* __restrict__ Wq, const float* __restrict__ Wk,
               const float* __restrict__ Wv, const float* __restrict__ Wo,
               bf16* __restrict__ Xh, bf16* __restrict__ Xl,
               bf16* __restrict__ qkvh, bf16* __restrict__ qkvl,
               bf16* __restrict__ oh, bf16* __restrict__ ol)
{
    const long long bid = blockIdx.x;
    const float* src;
    bf16 *hi, *lo;
    long long base;                          // float4 index within chosen tensor
    if (bid < XBLKS) {
        src = X; hi = Xh; lo = Xl; base = bid * 256;
    } else {
        const long long r = bid - XBLKS;
        const int w = (int)(r / WBLKS);
        base = (r % WBLKS) * 256;
        src = (w == 0) ? Wq : (w == 1) ? Wk : (w == 2) ? Wv : Wo;
        if (w < 3) { hi = qkvh + (long long)w * HHHH; lo = qkvl + (long long)w * HHHH; }
        else       { hi = oh; lo = ol; }
    }
    const long long i = base + threadIdx.x;
    float4 v = *(const float4*)(src + i * 4);
    uint2 h, l;
    split2(make_float2(v.x, v.y), h.x, l.x);
    split2(make_float2(v.z, v.w), h.y, l.y);
    *(uint2*)(hi + i * 4) = h;
    *(uint2*)(lo + i * 4) = l;
}

// ---------------- GEMM config (shared) ----------------
constexpr int STAGE = 49152;
constexpr int OA_HI = 0, OA_LO = 16384, OB_HI = 32768, OB_LO = 40960;
constexpr int SMEM_DYN = 2 * STAGE;      // 96 KB -> 2 CTAs/SM

// R12 mainloop (proven best): per-ks phase-ordered loads, two syncs per iter.
#define GEMM_MAINLOOP(Kdim)                                                         \
    const int NC = (Kdim) / 64;                                                     \
    issue(0, 0);                                                                    \
    for (int it = 0; it < NC; it++) {                                               \
        const int buf = it & 1;                                                     \
        if (it + 1 < NC) { issue(it + 1, buf ^ 1); CPWAIT(1); }                     \
        else             { CPWAIT(0); }                                             \
        __syncthreads();                                                            \
        const uint32_t stg = sb + buf * STAGE;                                      \
        const uint32_t stAh = stg + OA_HI;                                          \
        const uint32_t stAl = stg + OA_LO;                                          \
        const uint32_t stBh = stg + OB_HI;                                          \
        const uint32_t stBl = stg + OB_LO;                                          \
        _Pragma("unroll")                                                           \
        for (int ks = 0; ks < 4; ks++) {                                            \
            const int ca = ks * 2 + (lane >> 4);                                    \
            const int rA0 = m0w + (lane & 15);                                      \
            const int rB = n0w + lane;                                              \
            uint32_t ah[2][4];                                                      \
            _Pragma("unroll")                                                       \
            for (int mf = 0; mf < 2; mf++)                                          \
                LDSM4(ah[mf][0], ah[mf][1], ah[mf][2], ah[mf][3],                   \
                      stAh + toff8(rA0 + mf * 16, ca));                             \
            uint32_t bh[4][2];                                                      \
            _Pragma("unroll")                                                       \
            for (int h = 0; h < 2; h++)                                             \
                LDSM4(bh[0][h], bh[1][h], bh[2][h], bh[3][h],                       \
                      stBh + toff8(rB, ks * 2 + h));                                \
            _Pragma("unroll")                                                       \
            for (int mf = 0; mf < 2; mf++)                                          \
                _Pragma("unroll")                                                   \
                for (int nf = 0; nf < 4; nf++)                                      \
                    MMA_BF16(acc[mf][nf][0], acc[mf][nf][1], acc[mf][nf][2], acc[mf][nf][3], \
                             ah[mf][0], ah[mf][1], ah[mf][2], ah[mf][3],            \
                             bh[nf][0], bh[nf][1]);                                 \
            {                                                                       \
                uint32_t bl[4][2];                                                  \
                _Pragma("unroll")                                                   \
                for (int h = 0; h < 2; h++)                                         \
                    LDSM4(bl[0][h], bl[1][h], bl[2][h], bl[3][h],                   \
                          stBl + toff8(rB, ks * 2 + h));                            \
                _Pragma("unroll")                                                   \
                for (int mf = 0; mf < 2; mf++)                                      \
                    _Pragma("unroll")                                               \
                    for (int nf = 0; nf < 4; nf++)                                  \
                        MMA_BF16(acc[mf][nf][0], acc[mf][nf][1], acc[mf][nf][2], acc[mf][nf][3], \
                                 ah[mf][0], ah[mf][1], ah[mf][2], ah[mf][3],        \
                                 bl[nf][0], bl[nf][1]);                             \
            }                                                                       \
            {                                                                       \
                uint32_t al[2][4];                                                  \
                _Pragma("unroll")                                                   \
                for (int mf = 0; mf < 2; mf++)                                      \
                    LDSM4(al[mf][0], al[mf][1], al[mf][2], al[mf][3],               \
                          stAl + toff8(rA0 + mf * 16, ca));                         \
                _Pragma("unroll")                                                   \
                for (int mf = 0; mf < 2; mf++)                                      \
                    _Pragma("unroll")                                               \
                    for (int nf = 0; nf < 4; nf++)                                  \
                        MMA_BF16(acc[mf][nf][0], acc[mf][nf][1], acc[mf][nf][2], acc[mf][nf][3], \
                                 al[mf][0], al[mf][1], al[mf][2], al[mf][3],        \
                                 bh[nf][0], bh[nf][1]);                             \
            }                                                                       \
        }                                                                           \
        __syncthreads();                                                            \
    }

// ---------------- fused QKV projection GEMM ----------------
// z=0: Q (split out + wdd partials), z=1: K (split out), z=2: V (transposed split out)
__global__ __launch_bounds__(256, 2)
void tgemm_qkv(const bf16* __restrict__ Ah, const bf16* __restrict__ Al,
               const bf16* __restrict__ Wh, const bf16* __restrict__ Wl,
               const float* __restrict__ bq, const float* __restrict__ bk,
               const float* __restrict__ bv,
               bf16* __restrict__ QKh, bf16* __restrict__ QKl,
               bf16* __restrict__ Vth, bf16* __restrict__ Vtl,
               float* __restrict__ wddp, const float* __restrict__ dist1)
{
    extern __shared__ __align__(128) uint8_t sm[];
    const uint32_t sb = smem_u32(sm);
    const int tid = threadIdx.x;
    const int wid = tid >> 5;
    const int lane = tid & 31;
    const int z = blockIdx.z;
    const int row0 = blockIdx.y * 128;
    const int col0 = blockIdx.x * 64;
    const bf16* Ahp = Ah;
    const bf16* Alp = Al;
    const bf16* Bhp = Wh + (long long)z * HHHH;
    const bf16* Blp = Wl + (long long)z * HHHH;

    const int m0w = (wid & 3) * 32;
    const int n0w = (wid >> 2) * 32;
    const int rl = tid >> 3;
    const int cl = tid & 7;

    float acc[2][4][4];
    #pragma unroll
    for (int i = 0; i < 2; i++)
        #pragma unroll
        for (int j = 0; j < 4; j++)
            #pragma unroll
            for (int c = 0; c < 4; c++) acc[i][j][c] = 0.f;

    auto issue = [&](int it, int buf) {
        const int k0 = it * 64;
        const uint32_t st = sb + buf * STAGE;
        #pragma unroll
        for (int rr = 0; rr < 128; rr += 32) {
            const int r = rl + rr;
            const uint32_t o = toff8(r, cl);
            const long long aoff = (long long)(row0 + r) * HH + k0 + cl * 8;
            CP16(st + OA_HI + o, Ahp + aoff);
            CP16(st + OA_LO + o, Alp + aoff);
        }
        #pragma unroll
        for (int rr = 0; rr < 64; rr += 32) {
            const int r = rl + rr;
            const uint32_t o = toff8(r, cl);
            const long long boff = (long long)(col0 + r) * HH + k0 + cl * 8;
            CP16(st + OB_HI + o, Bhp + boff);
            CP16(st + OB_LO + o, Blp + boff);
        }
        CPCOMMIT();
    };

    GEMM_MAINLOOP(HH)

    const float* bias = (z == 0) ? bq : (z == 1) ? bk : bv;
    const int cr = lane >> 2;
    const int cc = (lane & 3) * 2;
    #pragma unroll
    for (int mf = 0; mf < 2; mf++) {
        #pragma unroll
        for (int half = 0; half < 2; half++) {
            const int r = row0 + m0w + mf * 16 + cr + half * 8;
            float wpart = 0.f;
            #pragma unroll
            for (int nf = 0; nf < 4; nf++) {
                const int c = col0 + n0w + nf * 8 + cc;
                float2 v;
                v.x = acc[mf][nf][half * 2 + 0] + bias[c];
                v.y = acc[mf][nf][half * 2 + 1] + bias[c + 1];
                if (z < 2) {
                    const long long rb = (long long)z * MMHH + (long long)r * HH;
                    uint32_t h, l;
                    split2(v, h, l);
                    *(uint32_t*)(QKh + rb + c) = h;
                    *(uint32_t*)(QKl + rb + c) = l;
                    if (z == 0) {
                        float2 dv = *(const float2*)(dist1 + c);
                        wpart = fmaf(v.x, dv.x, fmaf(v.y, dv.y, wpart));
                    }
                } else {
                    const int b = r >> 11;
                    const int s = r & (SS - 1);
                    const long long base = (long long)b * HH * SS + s;
                    bf162 h2 = __float22bfloat162_rn(v);
                    float2 hf = __bfloat1622float2(h2);
                    bf162 l2 = __float22bfloat162_rn(make_float2(v.x - hf.x, v.y - hf.y));
                    Vth[base + (long long)c * SS]       = h2.x;
                    Vth[base + (long long)(c + 1) * SS] = h2.y;
                    Vtl[base + (long long)c * SS]       = l2.x;
                    Vtl[base + (long long)(c + 1) * SS] = l2.y;
                }
            }
            if (z == 0) {
                wpart += __shfl_xor_sync(0xffffffffu, wpart, 1);
                wpart += __shfl_xor_sync(0xffffffffu, wpart, 2);
                if ((lane & 3) == 0)
                    wddp[(long long)r * 32 + blockIdx.x * 2 + (wid >> 2)] = wpart;
            }
        }
    }
}

// ---------------- generic split-bf16 GEMM (scores / PV / out-proj) ----------------
// OUTMODE 0: fp32 out (+bias +resid). OUTMODE 1: bf16 hi/lo out.
template<int OUTMODE>
__global__ __launch_bounds__(256, 2)
void tgemm(const bf16* __restrict__ Ah, const bf16* __restrict__ Al,
           const bf16* __restrict__ Bh, const bf16* __restrict__ Bl,
           const float* __restrict__ bias, const float* __restrict__ resid,
           float* __restrict__ Cf, bf16* __restrict__ Ch, bf16* __restrict__ Cl,
           int N, int K, long long sA, long long sB, long long sC)
{
    extern __shared__ __align__(128) uint8_t sm[];
    const uint32_t sb = smem_u32(sm);
    const int tid = threadIdx.x;
    const int wid = tid >> 5;
    const int lane = tid & 31;
    const int row0 = blockIdx.y * 128;
    const int col0 = blockIdx.x * 64;
    const bf16* Ahp = Ah + blockIdx.z * sA;
    const bf16* Alp = Al + blockIdx.z * sA;
    const bf16* Bhp = Bh + blockIdx.z * sB;
    const bf16* Blp = Bl + blockIdx.z * sB;

    const int m0w = (wid & 3) * 32;
    const int n0w = (wid >> 2) * 32;
    const int rl = tid >> 3;
    const int cl = tid & 7;

    float acc[2][4][4];
    #pragma unroll
    for (int i = 0; i < 2; i++)
        #pragma unroll
        for (int j = 0; j < 4; j++)
            #pragma unroll
            for (int c = 0; c < 4; c++) acc[i][j][c] = 0.f;

    auto issue = [&](int it, int buf) {
        const int k0 = it * 64;
        const uint32_t st = sb + buf * STAGE;
        #pragma unroll
        for (int rr = 0; rr < 128; rr += 32) {
            const int r = rl + rr;
            const uint32_t o = toff8(r, cl);
            const long long aoff = (long long)(row0 + r) * K + k0 + cl * 8;
            CP16(st + OA_HI + o, Ahp + aoff);
            CP16(st + OA_LO + o, Alp + aoff);
        }
        #pragma unroll
        for (int rr = 0; rr < 64; rr += 32) {
            const int r = rl + rr;
            const uint32_t o = toff8(r, cl);
            const long long boff = (long long)(col0 + r) * K + k0 + cl * 8;
            CP16(st + OB_HI + o, Bhp + boff);
            CP16(st + OB_LO + o, Blp + boff);
        }
        CPCOMMIT();
    };

    GEMM_MAINLOOP(K)

    const int cr = lane >> 2;
    const int cc = (lane & 3) * 2;
    #pragma unroll
    for (int mf = 0; mf < 2; mf++) {
        #pragma unroll
        for (int half = 0; half < 2; half++) {
            const int r = row0 + m0w + mf * 16 + cr + half * 8;
            const long long rb = (long long)r * N;
            #pragma unroll
            for (int nf = 0; nf < 4; nf++) {
                const int c = col0 + n0w + nf * 8 + cc;
                float2 v;
                v.x = acc[mf][nf][half * 2 + 0];
                v.y = acc[mf][nf][half * 2 + 1];
                if (bias) {
                    float2 bv = *(const float2*)(bias + c);
                    v.x += bv.x; v.y += bv.y;
                }
                if (OUTMODE == 0) {
                    if (resid) {
                        float2 rv = *(const float2*)(resid + blockIdx.z * sC + rb + c);
                        v.x += rv.x; v.y += rv.y;
                    }
                    *(float2*)(Cf + blockIdx.z * sC + rb + c) = v;
                } else {
                    uint32_t h, l;
                    split2(v, h, l);
                    *(uint32_t*)(Ch + blockIdx.z * sC + rb + c) = h;
                    *(uint32_t*)(Cl + blockIdx.z * sC + rb + c) = l;
                }
            }
        }
    }
}

// ---------------- softmax -> P hi/lo (512 threads, one float4/thread) ----------------
__global__ __launch_bounds__(512)
void softmax_kernel(const float* __restrict__ S, const int* __restrict__ rel,
                    const float* __restrict__ mask, const float* __restrict__ wddp,
                    bf16* __restrict__ Ph, bf16* __restrict__ Pl)
{
    const long long row = blockIdx.x;
    const int b = (int)(row >> 11);
    const float4* s4 = (const float4*)(S + row * (long long)SS);
    const int4*   r4 = (const int4*)(rel + row * (long long)SS);
    const float4* m4 = (const float4*)(mask + (long long)b * SS);

    __shared__ float swdd;
    if (threadIdx.x < 32) {
        float p = wddp[row * 32 + threadIdx.x];
        #pragma unroll
        for (int o = 16; o; o >>= 1) p += __shfl_xor_sync(0xffffffffu, p, o);
        if (threadIdx.x == 0) swdd = p;
    }
    __syncthreads();
    const float w = swdd;

    const int idx = threadIdx.x;
    float4 sv = s4[idx];
    int4   rv = r4[idx];
    float4 mv = m4[idx];
    sv.x = (rv.x == 1 ? sv.x + w : sv.x) * 0.03125f + mv.x;
    sv.y = (rv.y == 1 ? sv.y + w : sv.y) * 0.03125f + mv.y;
    sv.z = (rv.z == 1 ? sv.z + w : sv.z) * 0.03125f + mv.z;
    sv.w = (rv.w == 1 ? sv.w + w : sv.w) * 0.03125f + mv.w;
    float mx = fmaxf(fmaxf(sv.x, sv.y), fmaxf(sv.z, sv.w));

    __shared__ float shm[16], shs[16];
    #pragma unroll
    for (int o = 16; o; o >>= 1) mx = fmaxf(mx, __shfl_xor_sync(0xffffffffu, mx, o));
    if ((threadIdx.x & 31) == 0) shm[threadIdx.x >> 5] = mx;
    __syncthreads();
    mx = shm[0];
    #pragma unroll
    for (int i = 1; i < 16; i++) mx = fmaxf(mx, shm[i]);

    sv.x = __expf(sv.x - mx);
    sv.y = __expf(sv.y - mx);
    sv.z = __expf(sv.z - mx);
    sv.w = __expf(sv.w - mx);
    float tot = sv.x + sv.y + sv.z + sv.w;
    #pragma unroll
    for (int o = 16; o; o >>= 1) tot += __shfl_xor_sync(0xffffffffu, tot, o);
    if ((threadIdx.x & 31) == 0) shs[threadIdx.x >> 5] = tot;
    __syncthreads();
    tot = 0.f;
    #pragma unroll
    for (int i = 0; i < 16; i++) tot += shs[i];

    const float inv = 1.f / tot;
    sv.x *= inv; sv.y *= inv; sv.z *= inv; sv.w *= inv;
    uint2 h, l;
    split2(make_float2(sv.x, sv.y), h.x, l.x);
    split2(make_float2(sv.z, sv.w), h.y, l.y);
    ((uint2*)(Ph + row * (long long)SS))[idx] = h;
    ((uint2*)(Pl + row * (long long)SS))[idx] = l;
}

// ---------------- LayerNorm (vectorized) ----------------
__global__ __launch_bounds__(256)
void ln_kernel(const float* __restrict__ X, const float* __restrict__ g,
               const float* __restrict__ bb, float* __restrict__ out)
{
    const long long row = blockIdx.x;
    const float4* x4 = (const float4*)(X + row * HH);
    float4 v = x4[threadIdx.x];
    float sum = v.x + v.y + v.z + v.w;
    float sq = fmaf(v.x, v.x, fmaf(v.y, v.y, fmaf(v.z, v.z, v.w * v.w)));

    __shared__ float s1[8], s2[8];
    #pragma unroll
    for (int o = 16; o; o >>= 1) {
        sum += __shfl_xor_sync(0xffffffffu, sum, o);
        sq  += __shfl_xor_sync(0xffffffffu, sq, o);
    }
    if ((threadIdx.x & 31) == 0) { s1[threadIdx.x >> 5] = sum; s2[threadIdx.x >> 5] = sq; }
    __syncthreads();
    sum = 0.f; sq = 0.f;
    #pragma unroll
    for (int i = 0; i < 8; i++) { sum += s1[i]; sq += s2[i]; }

    const float mean = sum * (1.f / HH);
    const float var  = sq * (1.f / HH) - mean * mean;
    const float inv  = rsqrtf(var + 1e-12f);

    const float4 gv = ((const float4*)g)[threadIdx.x];
    const float4 bv = ((const float4*)bb)[threadIdx.x];
    float4 o;
    o.x = (v.x - mean) * inv * gv.x + bv.x;
    o.y = (v.y - mean) * inv * gv.y + bv.y;
    o.z = (v.z - mean) * inv * gv.z + bv.z;
    o.w = (v.w - mean) * inv * gv.w + bv.w;
    ((float4*)(out + row * HH))[threadIdx.x] = o;
}

// ---------------- launch ----------------
extern "C" void kernel_launch(void* const* d_in, const int* in_sizes, int n_in,
                              void* d_out, int out_size)
{
    const float* hidden = (const float*)d_in[0];
    const float* amask  = (const float*)d_in[1];
    const int*   rel    = (const int*)d_in[2];
    const float* Wq = (const float*)d_in[3];
    const float* bq = (const float*)d_in[4];
    const float* Wk = (const float*)d_in[5];
    const float* bk = (const float*)d_in[6];
    const float* Wv = (const float*)d_in[7];
    const float* bv = (const float*)d_in[8];
    const float* dist = (const float*)d_in[9];
    const float* Wo = (const float*)d_in[10];
    const float* bo = (const float*)d_in[11];
    const float* lng = (const float*)d_in[12];
    const float* lnb = (const float*)d_in[13];
    float* out = (float*)d_out;

    bf16 *Xh,*Xl,*Wqkvh,*Wqkvl,*Woh,*Wol;
    bf16 *QKh,*QKl,*Vth,*Vtl,*Ph,*Pl,*Ch,*Cl;
    float *Sp,*Xp,*Wpp;
    cudaGetSymbolAddress((void**)&Xh, g_Xh);     cudaGetSymbolAddress((void**)&Xl, g_Xl);
    cudaGetSymbolAddress((void**)&Wqkvh, g_Wqkvh); cudaGetSymbolAddress((void**)&Wqkvl, g_Wqkvl);
    cudaGetSymbolAddress((void**)&Woh, g_Woh);   cudaGetSymbolAddress((void**)&Wol, g_Wol);
    cudaGetSymbolAddress((void**)&QKh, g_QKh);   cudaGetSymbolAddress((void**)&QKl, g_QKl);
    cudaGetSymbolAddress((void**)&Vth, g_Vth);   cudaGetSymbolAddress((void**)&Vtl, g_Vtl);
    cudaGetSymbolAddress((void**)&Ph, g_Ph);     cudaGetSymbolAddress((void**)&Pl, g_Pl);
    cudaGetSymbolAddress((void**)&Ch, g_Ch);     cudaGetSymbolAddress((void**)&Cl, g_Cl);
    cudaGetSymbolAddress((void**)&Sp, g_S);
    cudaGetSymbolAddress((void**)&Xp, g_x);
    cudaGetSymbolAddress((void**)&Wpp, g_wddp);

    cudaFuncSetAttribute(tgemm_qkv, cudaFuncAttributeMaxDynamicSharedMemorySize, SMEM_DYN);
    cudaFuncSetAttribute(tgemm<0>, cudaFuncAttributeMaxDynamicSharedMemorySize, SMEM_DYN);
    cudaFuncSetAttribute(tgemm<1>, cudaFuncAttributeMaxDynamicSharedMemorySize, SMEM_DYN);

    dim3 blk(256);

    // one fused split launch: X + Wq/Wk/Wv/Wo
    split_all<<<XBLKS + 4 * WBLKS, blk>>>(hidden, Wq, Wk, Wv, Wo,
                                          Xh, Xl, Wqkvh, Wqkvl, Woh, Wol);

    dim3 tb(256);
    // fused QKV projection: grid z = 0(Q),1(K),2(V)
    tgemm_qkv<<<dim3(HH / 64, MM / 128, 3), tb, SMEM_DYN>>>(
        Xh, Xl, Wqkvh, Wqkvl, bq, bk, bv,
        QKh, QKl, Vth, Vtl, Wpp, dist + HH);

    // scores: per batch QK^T -> fp32 S
    dim3 gs(SS / 64, SS / 128, BB);
    tgemm<0><<<gs, tb, SMEM_DYN>>>(QKh, QKl, QKh + MMHH, QKl + MMHH, nullptr, nullptr,
                                   Sp, nullptr, nullptr, SS, HH,
                                   (long long)SS * HH, (long long)SS * HH, (long long)SS * SS);

    // softmax -> P hi/lo (512 threads)
    softmax_kernel<<<MM, dim3(512)>>>(Sp, rel, amask, Wpp, Ph, Pl);

    // ctx: per batch P . Vt^T -> ctx hi/lo
    dim3 gp(HH / 64, SS / 128, BB);
    tgemm<1><<<gp, tb, SMEM_DYN>>>(Ph, Pl, Vth, Vtl, nullptr, nullptr,
                                   nullptr, Ch, Cl, HH, SS,
                                   (long long)SS * SS, (long long)HH * SS, (long long)SS * HH);

    // out projection + bias + residual -> fp32 x
    dim3 go(HH / 64, MM / 128, 1);
    tgemm<0><<<go, tb, SMEM_DYN>>>(Ch, Cl, Woh, Wol, bo, hidden,
                                   Xp, nullptr, nullptr, HH, HH, 0, 0, 0);

    ln_kernel<<<MM, blk>>>(Xp, lng, lnb, out);
}

// round 15
// speedup vs baseline: 1.0109x; 1.0069x over previous
#include <cuda_runtime.h>
#include <cuda_bf16.h>
#include <cstdint>

#define BB 4
#define SS 2048
#define HH 1024
#define MM (BB*SS)
#define HHHH ((long long)HH*HH)
#define MMHH ((long long)MM*HH)

typedef __nv_bfloat16 bf16;
typedef __nv_bfloat162 bf162;

// ---------------- scratch ----------------
__device__ bf16  g_Xh[MM*HH], g_Xl[MM*HH];
__device__ bf16  g_Wqkvh[3*HH*HH], g_Wqkvl[3*HH*HH];   // Wq|Wk|Wv contiguous slabs
__device__ bf16  g_Woh[HH*HH], g_Wol[HH*HH];
__device__ bf16  g_QKh[2*MM*HH], g_QKl[2*MM*HH];       // Q slab | K slab
__device__ bf16  g_Vth[MM*HH], g_Vtl[MM*HH];
__device__ float g_S[(long long)BB*SS*SS];
__device__ bf16  g_Ph[BB*SS*SS], g_Pl[BB*SS*SS];
__device__ bf16  g_Ch[MM*HH], g_Cl[MM*HH];
__device__ float g_x[(long long)MM*HH];
__device__ float g_wddp[MM*32];

// ---------------- helpers ----------------
__device__ __forceinline__ uint32_t smem_u32(const void* p){
    uint32_t a;
    asm("{ .reg .u64 t; cvta.to.shared.u64 t, %1; cvt.u32.u64 %0, t; }" : "=r"(a) : "l"(p));
    return a;
}
#define LDSM4(r0,r1,r2,r3,addr) \
    asm volatile("ldmatrix.sync.aligned.m8n8.x4.shared.b16 {%0,%1,%2,%3}, [%4];" \
        : "=r"(r0),"=r"(r1),"=r"(r2),"=r"(r3) : "r"(addr))
#define MMA_BF16(d0,d1,d2,d3, a0,a1,a2,a3, b0,b1) \
    asm volatile("mma.sync.aligned.m16n8k16.row.col.f32.bf16.bf16.f32 " \
        "{%0,%1,%2,%3}, {%4,%5,%6,%7}, {%8,%9}, {%0,%1,%2,%3};" \
        : "+f"(d0),"+f"(d1),"+f"(d2),"+f"(d3) \
        : "r"(a0),"r"(a1),"r"(a2),"r"(a3), "r"(b0),"r"(b1))
#define CP16(dst, src) asm volatile("cp.async.cg.shared.global [%0], [%1], 16;" :: "r"(dst), "l"(src))
#define CPCOMMIT() asm volatile("cp.async.commit_group;" ::: "memory")
#define CPWAIT(n)  asm volatile("cp.async.wait_group %0;" :: "n"(n) : "memory")

__device__ __forceinline__ uint32_t bfbits(bf162 h){ return *reinterpret_cast<uint32_t*>(&h); }

__device__ __forceinline__ void split2(float2 v, uint32_t& h, uint32_t& l){
    bf162 h2 = __float22bfloat162_rn(v);
    float2 hf = __bfloat1622float2(h2);
    bf162 l2 = __float22bfloat162_rn(make_float2(v.x - hf.x, v.y - hf.y));
    h = bfbits(h2); l = bfbits(l2);
}

// swizzled byte offset of 16B chunk (row r, k-chunk c in 0..7) in a [rows][64] bf16 tile
__device__ __forceinline__ uint32_t toff8(int r, int c){
    return (uint32_t)(r * 128 + ((c ^ (r & 7)) << 4));
}

// ---------------- fused split: X + all 4 weights in one launch ----------------
constexpr int XBLKS = MM * HH / 4 / 256;    // 8192
constexpr int WBLKS = HH * HH / 4 / 256;    // 1024

__global__ __launch_bounds__(256)
void split_all(const float* __restrict__ X,
               const float* __restrict__ Wq, const float* __restrict__ Wk,
               const float* __restrict__ Wv, const float* __restrict__ Wo,
               bf16* __restrict__ Xh, bf16* __restrict__ Xl,
               bf16* __restrict__ qkvh, bf16* __restrict__ qkvl,
               bf16* __restrict__ oh, bf16* __restrict__ ol)
{
    const long long bid = blockIdx.x;
    const float* src;
    bf16 *hi, *lo;
    long long base;
    if (bid < XBLKS) {
        src = X; hi = Xh; lo = Xl; base = bid * 256;
    } else {
        const long long r = bid - XBLKS;
        const int w = (int)(r / WBLKS);
        base = (r % WBLKS) * 256;
        src = (w == 0) ? Wq : (w == 1) ? Wk : (w == 2) ? Wv : Wo;
        if (w < 3) { hi = qkvh + (long long)w * HHHH; lo = qkvl + (long long)w * HHHH; }
        else       { hi = oh; lo = ol; }
    }
    const long long i = base + threadIdx.x;
    float4 v = *(const float4*)(src + i * 4);
    uint2 h, l;
    split2(make_float2(v.x, v.y), h.x, l.x);
    split2(make_float2(v.z, v.w), h.y, l.y);
    *(uint2*)(hi + i * 4) = h;
    *(uint2*)(lo + i * 4) = l;
}

// ---------------- GEMM config (shared) ----------------
constexpr int STAGE = 49152;
constexpr int OA_HI = 0, OA_LO = 16384, OB_HI = 32768, OB_LO = 40960;
constexpr int SMEM_DYN = 2 * STAGE;      // 96 KB -> 2 CTAs/SM

// R12 mainloop (proven best): per-ks phase-ordered loads, two syncs per iter.
#define GEMM_MAINLOOP(Kdim)                                                         \
    const int NC = (Kdim) / 64;                                                     \
    issue(0, 0);                                                                    \
    for (int it = 0; it < NC; it++) {                                               \
        const int buf = it & 1;                                                     \
        if (it + 1 < NC) { issue(it + 1, buf ^ 1); CPWAIT(1); }                     \
        else             { CPWAIT(0); }                                             \
        __syncthreads();                                                            \
        const uint32_t stg = sb + buf * STAGE;                                      \
        const uint32_t stAh = stg + OA_HI;                                          \
        const uint32_t stAl = stg + OA_LO;                                          \
        const uint32_t stBh = stg + OB_HI;                                          \
        const uint32_t stBl = stg + OB_LO;                                          \
        _Pragma("unroll")                                                           \
        for (int ks = 0; ks < 4; ks++) {                                            \
            const int ca = ks * 2 + (lane >> 4);                                    \
            const int rA0 = m0w + (lane & 15);                                      \
            const int rB = n0w + lane;                                              \
            uint32_t ah[2][4];                                                      \
            _Pragma("unroll")                                                       \
            for (int mf = 0; mf < 2; mf++)                                          \
                LDSM4(ah[mf][0], ah[mf][1], ah[mf][2], ah[mf][3],                   \
                      stAh + toff8(rA0 + mf * 16, ca));                             \
            uint32_t bh[4][2];                                                      \
            _Pragma("unroll")                                                       \
            for (int h = 0; h < 2; h++)                                             \
                LDSM4(bh[0][h], bh[1][h], bh[2][h], bh[3][h],                       \
                      stBh + toff8(rB, ks * 2 + h));                                \
            _Pragma("unroll")                                                       \
            for (int mf = 0; mf < 2; mf++)                                          \
                _Pragma("unroll")                                                   \
                for (int nf = 0; nf < 4; nf++)                                      \
                    MMA_BF16(acc[mf][nf][0], acc[mf][nf][1], acc[mf][nf][2], acc[mf][nf][3], \
                             ah[mf][0], ah[mf][1], ah[mf][2], ah[mf][3],            \
                             bh[nf][0], bh[nf][1]);                                 \
            {                                                                       \
                uint32_t bl[4][2];                                                  \
                _Pragma("unroll")                                                   \
                for (int h = 0; h < 2; h++)                                         \
                    LDSM4(bl[0][h], bl[1][h], bl[2][h], bl[3][h],                   \
                          stBl + toff8(rB, ks * 2 + h));                            \
                _Pragma("unroll")                                                   \
                for (int mf = 0; mf < 2; mf++)                                      \
                    _Pragma("unroll")                                               \
                    for (int nf = 0; nf < 4; nf++)                                  \
                        MMA_BF16(acc[mf][nf][0], acc[mf][nf][1], acc[mf][nf][2], acc[mf][nf][3], \
                                 ah[mf][0], ah[mf][1], ah[mf][2], ah[mf][3],        \
                                 bl[nf][0], bl[nf][1]);                             \
            }                                                                       \
            {                                                                       \
                uint32_t al[2][4];                                                  \
                _Pragma("unroll")                                                   \
                for (int mf = 0; mf < 2; mf++)                                      \
                    LDSM4(al[mf][0], al[mf][1], al[mf][2], al[mf][3],               \
                          stAl + toff8(rA0 + mf * 16, ca));                         \
                _Pragma("unroll")                                                   \
                for (int mf = 0; mf < 2; mf++)                                      \
                    _Pragma("unroll")                                               \
                    for (int nf = 0; nf < 4; nf++)                                  \
                        MMA_BF16(acc[mf][nf][0], acc[mf][nf][1], acc[mf][nf][2], acc[mf][nf][3], \
                                 al[mf][0], al[mf][1], al[mf][2], al[mf][3],        \
                                 bh[nf][0], bh[nf][1]);                             \
            }                                                                       \
        }                                                                           \
        __syncthreads();                                                            \
    }

// ---------------- fused QKV projection GEMM ----------------
// z=0: Q (split out + wdd partials), z=1: K (split out), z=2: V (transposed split out)
__global__ __launch_bounds__(256, 2)
void tgemm_qkv(const bf16* __restrict__ Ah, const bf16* __restrict__ Al,
               const bf16* __restrict__ Wh, const bf16* __restrict__ Wl,
               const float* __restrict__ bq, const float* __restrict__ bk,
               const float* __restrict__ bv,
               bf16* __restrict__ QKh, bf16* __restrict__ QKl,
               bf16* __restrict__ Vth, bf16* __restrict__ Vtl,
               float* __restrict__ wddp, const float* __restrict__ dist1)
{
    extern __shared__ __align__(128) uint8_t sm[];
    const uint32_t sb = smem_u32(sm);
    const int tid = threadIdx.x;
    const int wid = tid >> 5;
    const int lane = tid & 31;
    const int z = blockIdx.z;
    const int row0 = blockIdx.y * 128;
    const int col0 = blockIdx.x * 64;
    const bf16* Ahp = Ah;
    const bf16* Alp = Al;
    const bf16* Bhp = Wh + (long long)z * HHHH;
    const bf16* Blp = Wl + (long long)z * HHHH;

    const int m0w = (wid & 3) * 32;
    const int n0w = (wid >> 2) * 32;
    const int rl = tid >> 3;
    const int cl = tid & 7;

    float acc[2][4][4];
    #pragma unroll
    for (int i = 0; i < 2; i++)
        #pragma unroll
        for (int j = 0; j < 4; j++)
            #pragma unroll
            for (int c = 0; c < 4; c++) acc[i][j][c] = 0.f;

    auto issue = [&](int it, int buf) {
        const int k0 = it * 64;
        const uint32_t st = sb + buf * STAGE;
        #pragma unroll
        for (int rr = 0; rr < 128; rr += 32) {
            const int r = rl + rr;
            const uint32_t o = toff8(r, cl);
            const long long aoff = (long long)(row0 + r) * HH + k0 + cl * 8;
            CP16(st + OA_HI + o, Ahp + aoff);
            CP16(st + OA_LO + o, Alp + aoff);
        }
        #pragma unroll
        for (int rr = 0; rr < 64; rr += 32) {
            const int r = rl + rr;
            const uint32_t o = toff8(r, cl);
            const long long boff = (long long)(col0 + r) * HH + k0 + cl * 8;
            CP16(st + OB_HI + o, Bhp + boff);
            CP16(st + OB_LO + o, Blp + boff);
        }
        CPCOMMIT();
    };

    GEMM_MAINLOOP(HH)

    const float* bias = (z == 0) ? bq : (z == 1) ? bk : bv;
    const int cr = lane >> 2;
    const int cc = (lane & 3) * 2;
    #pragma unroll
    for (int mf = 0; mf < 2; mf++) {
        #pragma unroll
        for (int half = 0; half < 2; half++) {
            const int r = row0 + m0w + mf * 16 + cr + half * 8;
            float wpart = 0.f;
            #pragma unroll
            for (int nf = 0; nf < 4; nf++) {
                const int c = col0 + n0w + nf * 8 + cc;
                float2 v;
                v.x = acc[mf][nf][half * 2 + 0] + bias[c];
                v.y = acc[mf][nf][half * 2 + 1] + bias[c + 1];
                if (z < 2) {
                    const long long rb = (long long)z * MMHH + (long long)r * HH;
                    uint32_t h, l;
                    split2(v, h, l);
                    *(uint32_t*)(QKh + rb + c) = h;
                    *(uint32_t*)(QKl + rb + c) = l;
                    if (z == 0) {
                        float2 dv = *(const float2*)(dist1 + c);
                        wpart = fmaf(v.x, dv.x, fmaf(v.y, dv.y, wpart));
                    }
                } else {
                    const int b = r >> 11;
                    const int s = r & (SS - 1);
                    const long long base = (long long)b * HH * SS + s;
                    bf162 h2 = __float22bfloat162_rn(v);
                    float2 hf = __bfloat1622float2(h2);
                    bf162 l2 = __float22bfloat162_rn(make_float2(v.x - hf.x, v.y - hf.y));
                    Vth[base + (long long)c * SS]       = h2.x;
                    Vth[base + (long long)(c + 1) * SS] = h2.y;
                    Vtl[base + (long long)c * SS]       = l2.x;
                    Vtl[base + (long long)(c + 1) * SS] = l2.y;
                }
            }
            if (z == 0) {
                wpart += __shfl_xor_sync(0xffffffffu, wpart, 1);
                wpart += __shfl_xor_sync(0xffffffffu, wpart, 2);
                if ((lane & 3) == 0)
                    wddp[(long long)r * 32 + blockIdx.x * 2 + (wid >> 2)] = wpart;
            }
        }
    }
}

// ---------------- generic split-bf16 GEMM (scores / PV / out-proj) ----------------
// OUTMODE 0: fp32 out (+bias +resid). OUTMODE 1: bf16 hi/lo out.
template<int OUTMODE>
__global__ __launch_bounds__(256, 2)
void tgemm(const bf16* __restrict__ Ah, const bf16* __restrict__ Al,
           const bf16* __restrict__ Bh, const bf16* __restrict__ Bl,
           const float* __restrict__ bias, const float* __restrict__ resid,
           float* __restrict__ Cf, bf16* __restrict__ Ch, bf16* __restrict__ Cl,
           int N, int K, long long sA, long long sB, long long sC)
{
    extern __shared__ __align__(128) uint8_t sm[];
    const uint32_t sb = smem_u32(sm);
    const int tid = threadIdx.x;
    const int wid = tid >> 5;
    const int lane = tid & 31;
    const int row0 = blockIdx.y * 128;
    const int col0 = blockIdx.x * 64;
    const bf16* Ahp = Ah + blockIdx.z * sA;
    const bf16* Alp = Al + blockIdx.z * sA;
    const bf16* Bhp = Bh + blockIdx.z * sB;
    const bf16* Blp = Bl + blockIdx.z * sB;

    const int m0w = (wid & 3) * 32;
    const int n0w = (wid >> 2) * 32;
    const int rl = tid >> 3;
    const int cl = tid & 7;

    float acc[2][4][4];
    #pragma unroll
    for (int i = 0; i < 2; i++)
        #pragma unroll
        for (int j = 0; j < 4; j++)
            #pragma unroll
            for (int c = 0; c < 4; c++) acc[i][j][c] = 0.f;

    auto issue = [&](int it, int buf) {
        const int k0 = it * 64;
        const uint32_t st = sb + buf * STAGE;
        #pragma unroll
        for (int rr = 0; rr < 128; rr += 32) {
            const int r = rl + rr;
            const uint32_t o = toff8(r, cl);
            const long long aoff = (long long)(row0 + r) * K + k0 + cl * 8;
            CP16(st + OA_HI + o, Ahp + aoff);
            CP16(st + OA_LO + o, Alp + aoff);
        }
        #pragma unroll
        for (int rr = 0; rr < 64; rr += 32) {
            const int r = rl + rr;
            const uint32_t o = toff8(r, cl);
            const long long boff = (long long)(col0 + r) * K + k0 + cl * 8;
            CP16(st + OB_HI + o, Bhp + boff);
            CP16(st + OB_LO + o, Blp + boff);
        }
        CPCOMMIT();
    };

    GEMM_MAINLOOP(K)

    const int cr = lane >> 2;
    const int cc = (lane & 3) * 2;
    #pragma unroll
    for (int mf = 0; mf < 2; mf++) {
        #pragma unroll
        for (int half = 0; half < 2; half++) {
            const int r = row0 + m0w + mf * 16 + cr + half * 8;
            const long long rb = (long long)r * N;
            #pragma unroll
            for (int nf = 0; nf < 4; nf++) {
                const int c = col0 + n0w + nf * 8 + cc;
                float2 v;
                v.x = acc[mf][nf][half * 2 + 0];
                v.y = acc[mf][nf][half * 2 + 1];
                if (bias) {
                    float2 bv = *(const float2*)(bias + c);
                    v.x += bv.x; v.y += bv.y;
                }
                if (OUTMODE == 0) {
                    if (resid) {
                        float2 rv = *(const float2*)(resid + blockIdx.z * sC + rb + c);
                        v.x += rv.x; v.y += rv.y;
                    }
                    *(float2*)(Cf + blockIdx.z * sC + rb + c) = v;
                } else {
                    uint32_t h, l;
                    split2(v, h, l);
                    *(uint32_t*)(Ch + blockIdx.z * sC + rb + c) = h;
                    *(uint32_t*)(Cl + blockIdx.z * sC + rb + c) = l;
                }
            }
        }
    }
}

// ---------------- softmax -> P hi/lo (256 threads, R12 version) ----------------
__global__ __launch_bounds__(256)
void softmax_kernel(const float* __restrict__ S, const int* __restrict__ rel,
                    const float* __restrict__ mask, const float* __restrict__ wddp,
                    bf16* __restrict__ Ph, bf16* __restrict__ Pl)
{
    const long long row = blockIdx.x;
    const int b = (int)(row >> 11);
    const float4* s4 = (const float4*)(S + row * (long long)SS);
    const int4*   r4 = (const int4*)(rel + row * (long long)SS);
    const float4* m4 = (const float4*)(mask + (long long)b * SS);

    __shared__ float swdd;
    if (threadIdx.x < 32) {
        float p = wddp[row * 32 + threadIdx.x];
        #pragma unroll
        for (int o = 16; o; o >>= 1) p += __shfl_xor_sync(0xffffffffu, p, o);
        if (threadIdx.x == 0) swdd = p;
    }
    __syncthreads();
    const float w = swdd;

    float4 vals[2];
    float mx = -1e30f;
    #pragma unroll
    for (int i = 0; i < 2; i++) {
        const int idx = threadIdx.x + i * 256;
        float4 sv = s4[idx];
        int4   rv = r4[idx];
        float4 mv = m4[idx];
        sv.x = (rv.x == 1 ? sv.x + w : sv.x) * 0.03125f + mv.x;
        sv.y = (rv.y == 1 ? sv.y + w : sv.y) * 0.03125f + mv.y;
        sv.z = (rv.z == 1 ? sv.z + w : sv.z) * 0.03125f + mv.z;
        sv.w = (rv.w == 1 ? sv.w + w : sv.w) * 0.03125f + mv.w;
        vals[i] = sv;
        mx = fmaxf(mx, fmaxf(fmaxf(sv.x, sv.y), fmaxf(sv.z, sv.w)));
    }
    __shared__ float shm[8], shs[8];
    #pragma unroll
    for (int o = 16; o; o >>= 1) mx = fmaxf(mx, __shfl_xor_sync(0xffffffffu, mx, o));
    if ((threadIdx.x & 31) == 0) shm[threadIdx.x >> 5] = mx;
    __syncthreads();
    mx = shm[0];
    #pragma unroll
    for (int i = 1; i < 8; i++) mx = fmaxf(mx, shm[i]);

    float tot = 0.f;
    #pragma unroll
    for (int i = 0; i < 2; i++) {
        vals[i].x = __expf(vals[i].x - mx);
        vals[i].y = __expf(vals[i].y - mx);
        vals[i].z = __expf(vals[i].z - mx);
        vals[i].w = __expf(vals[i].w - mx);
        tot += vals[i].x + vals[i].y + vals[i].z + vals[i].w;
    }
    #pragma unroll
    for (int o = 16; o; o >>= 1) tot += __shfl_xor_sync(0xffffffffu, tot, o);
    if ((threadIdx.x & 31) == 0) shs[threadIdx.x >> 5] = tot;
    __syncthreads();
    tot = 0.f;
    #pragma unroll
    for (int i = 0; i < 8; i++) tot += shs[i];

    const float inv = 1.f / tot;
    uint2* ph2 = (uint2*)(Ph + row * (long long)SS);
    uint2* pl2 = (uint2*)(Pl + row * (long long)SS);
    #pragma unroll
    for (int i = 0; i < 2; i++) {
        const int idx = threadIdx.x + i * 256;
        float4 p = vals[i];
        p.x *= inv; p.y *= inv; p.z *= inv; p.w *= inv;
        uint2 h, l;
        split2(make_float2(p.x, p.y), h.x, l.x);
        split2(make_float2(p.z, p.w), h.y, l.y);
        ph2[idx] = h;
        pl2[idx] = l;
    }
}

// ---------------- LayerNorm (vectorized) ----------------
__global__ __launch_bounds__(256)
void ln_kernel(const float* __restrict__ X, const float* __restrict__ g,
               const float* __restrict__ bb, float* __restrict__ out)
{
    const long long row = blockIdx.x;
    const float4* x4 = (const float4*)(X + row * HH);
    float4 v = x4[threadIdx.x];
    float sum = v.x + v.y + v.z + v.w;
    float sq = fmaf(v.x, v.x, fmaf(v.y, v.y, fmaf(v.z, v.z, v.w * v.w)));

    __shared__ float s1[8], s2[8];
    #pragma unroll
    for (int o = 16; o; o >>= 1) {
        sum += __shfl_xor_sync(0xffffffffu, sum, o);
        sq  += __shfl_xor_sync(0xffffffffu, sq, o);
    }
    if ((threadIdx.x & 31) == 0) { s1[threadIdx.x >> 5] = sum; s2[threadIdx.x >> 5] = sq; }
    __syncthreads();
    sum = 0.f; sq = 0.f;
    #pragma unroll
    for (int i = 0; i < 8; i++) { sum += s1[i]; sq += s2[i]; }

    const float mean = sum * (1.f / HH);
    const float var  = sq * (1.f / HH) - mean * mean;
    const float inv  = rsqrtf(var + 1e-12f);

    const float4 gv = ((const float4*)g)[threadIdx.x];
    const float4 bv = ((const float4*)bb)[threadIdx.x];
    float4 o;
    o.x = (v.x - mean) * inv * gv.x + bv.x;
    o.y = (v.y - mean) * inv * gv.y + bv.y;
    o.z = (v.z - mean) * inv * gv.z + bv.z;
    o.w = (v.w - mean) * inv * gv.w + bv.w;
    ((float4*)(out + row * HH))[threadIdx.x] = o;
}

// ---------------- launch ----------------
extern "C" void kernel_launch(void* const* d_in, const int* in_sizes, int n_in,
                              void* d_out, int out_size)
{
    const float* hidden = (const float*)d_in[0];
    const float* amask  = (const float*)d_in[1];
    const int*   rel    = (const int*)d_in[2];
    const float* Wq = (const float*)d_in[3];
    const float* bq = (const float*)d_in[4];
    const float* Wk = (const float*)d_in[5];
    const float* bk = (const float*)d_in[6];
    const float* Wv = (const float*)d_in[7];
    const float* bv = (const float*)d_in[8];
    const float* dist = (const float*)d_in[9];
    const float* Wo = (const float*)d_in[10];
    const float* bo = (const float*)d_in[11];
    const float* lng = (const float*)d_in[12];
    const float* lnb = (const float*)d_in[13];
    float* out = (float*)d_out;

    bf16 *Xh,*Xl,*Wqkvh,*Wqkvl,*Woh,*Wol;
    bf16 *QKh,*QKl,*Vth,*Vtl,*Ph,*Pl,*Ch,*Cl;
    float *Sp,*Xp,*Wpp;
    cudaGetSymbolAddress((void**)&Xh, g_Xh);     cudaGetSymbolAddress((void**)&Xl, g_Xl);
    cudaGetSymbolAddress((void**)&Wqkvh, g_Wqkvh); cudaGetSymbolAddress((void**)&Wqkvl, g_Wqkvl);
    cudaGetSymbolAddress((void**)&Woh, g_Woh);   cudaGetSymbolAddress((void**)&Wol, g_Wol);
    cudaGetSymbolAddress((void**)&QKh, g_QKh);   cudaGetSymbolAddress((void**)&QKl, g_QKl);
    cudaGetSymbolAddress((void**)&Vth, g_Vth);   cudaGetSymbolAddress((void**)&Vtl, g_Vtl);
    cudaGetSymbolAddress((void**)&Ph, g_Ph);     cudaGetSymbolAddress((void**)&Pl, g_Pl);
    cudaGetSymbolAddress((void**)&Ch, g_Ch);     cudaGetSymbolAddress((void**)&Cl, g_Cl);
    cudaGetSymbolAddress((void**)&Sp, g_S);
    cudaGetSymbolAddress((void**)&Xp, g_x);
    cudaGetSymbolAddress((void**)&Wpp, g_wddp);

    cudaFuncSetAttribute(tgemm_qkv, cudaFuncAttributeMaxDynamicSharedMemorySize, SMEM_DYN);
    cudaFuncSetAttribute(tgemm<0>, cudaFuncAttributeMaxDynamicSharedMemorySize, SMEM_DYN);
    cudaFuncSetAttribute(tgemm<1>, cudaFuncAttributeMaxDynamicSharedMemorySize, SMEM_DYN);

    dim3 blk(256);

    // one fused split launch: X + Wq/Wk/Wv/Wo
    split_all<<<XBLKS + 4 * WBLKS, blk>>>(hidden, Wq, Wk, Wv, Wo,
                                          Xh, Xl, Wqkvh, Wqkvl, Woh, Wol);

    dim3 tb(256);
    // fused QKV projection: grid z = 0(Q),1(K),2(V)
    tgemm_qkv<<<dim3(HH / 64, MM / 128, 3), tb, SMEM_DYN>>>(
        Xh, Xl, Wqkvh, Wqkvl, bq, bk, bv,
        QKh, QKl, Vth, Vtl, Wpp, dist + HH);

    // scores: per batch QK^T -> fp32 S
    dim3 gs(SS / 64, SS / 128, BB);
    tgemm<0><<<gs, tb, SMEM_DYN>>>(QKh, QKl, QKh + MMHH, QKl + MMHH, nullptr, nullptr,
                                   Sp, nullptr, nullptr, SS, HH,
                                   (long long)SS * HH, (long long)SS * HH, (long long)SS * SS);

    // softmax -> P hi/lo
    softmax_kernel<<<MM, blk>>>(Sp, rel, amask, Wpp, Ph, Pl);

    // ctx: per batch P . Vt^T -> ctx hi/lo
    dim3 gp(HH / 64, SS / 128, BB);
    tgemm<1><<<gp, tb, SMEM_DYN>>>(Ph, Pl, Vth, Vtl, nullptr, nullptr,
                                   nullptr, Ch, Cl, HH, SS,
                                   (long long)SS * SS, (long long)HH * SS, (long long)SS * HH);

    // out projection + bias + residual -> fp32 x
    dim3 go(HH / 64, MM / 128, 1);
    tgemm<0><<<go, tb, SMEM_DYN>>>(Ch, Cl, Woh, Wol, bo, hidden,
                                   Xp, nullptr, nullptr, HH, HH, 0, 0, 0);

    ln_kernel<<<MM, blk>>>(Xp, lng, lnb, out);
}